// round 10
// baseline (speedup 1.0000x reference)
#include <cuda_runtime.h>
#include <math.h>
#include <stdint.h>

#define B_L   192
#define NVAL  325
#define NPAD  352
#define D     256
#define DPOS  64
#define KPROJ 320
#define HEADS 8
#define EDIM  32
#define BH    (B_L*HEADS)      /* 1536 */
#define NH    4
#define NB    22
#define NC    (NH*NB)          /* 88 */
#define BKTS  16
#define NS    (NH*NPAD)        /* 1408 */
#define MROWS (B_L*NPAD)       /* 67584 */
#define MVAL  (B_L*NVAL)       /* 62400 */
#define GRIDM 488              /* ceil(62400/128) */

typedef unsigned long long u64;

__device__ __forceinline__ u64 pack2(float x, float y) {
    u64 r; asm("mov.b64 %0,{%1,%2};" : "=l"(r) : "f"(x), "f"(y)); return r;
}
__device__ __forceinline__ void unpack2(u64 v, float& x, float& y) {
    asm("mov.b64 {%0,%1},%2;" : "=f"(x), "=f"(y) : "l"(v));
}
__device__ __forceinline__ u64 fma2(u64 a, u64 b, u64 c) {
    u64 d; asm("fma.rn.f32x2 %0,%1,%2,%3;" : "=l"(d) : "l"(a), "l"(b), "l"(c)); return d;
}

// ---------------- scratch -------------------------------------------------------
__device__ __align__(16) float g_h    [MROWS*D];
__device__ __align__(16) float g_qk   [BH*NPAD*EDIM];
__device__ __align__(16) float g_v    [BH*NPAD*EDIM];
__device__ int   g_bucket [BH*NS];
__device__ int   g_sticker[BH*NS];
__device__ __align__(16) float g_o    [BH*NH*NPAD*EDIM];
__device__ float g_lse  [BH*NH*NPAD];
__device__ __align__(16) float g_hcomb[MROWS*D];

// -------- 128x128 SGEMM over VALID rows, BK=16, 8x8/thread quadrants, FFMA2 ----
// (per-output-element k-chains bit-identical to the R4/R9 passing kernels)
// MODE 0: h = [x|ste] @ w_proj + b_proj (K=320) -> g_h (valid rows)
// MODE 1: [qk|v] = g_h @ [w_qk|w_v] (K=256, N=512) -> g_qk/g_v head-scatter
// MODE 2: out = g_hcomb @ w_out + b_out (K=256) -> d_out
template<int MODE>
__global__ __launch_bounds__(256, 2)
void gemm_k(const float* __restrict__ P0, const float* __restrict__ P1,
            const float* __restrict__ W0, const float* __restrict__ W1,
            const float* __restrict__ bias, float* __restrict__ Cout)
{
    constexpr int BM = 128, BN = 128, BK = 16;
    constexpr int KDIM = (MODE == 0) ? KPROJ : 256;
    constexpr int NT   = KDIM / BK;
    constexpr int LDA  = BM + 4;

    __shared__ float As[2][BK][LDA];
    __shared__ float Bs[2][BK][BN];

    const int tid = threadIdx.x;
    const int bm  = blockIdx.x * BM;
    const int bn  = blockIdx.y * BN;

    // ---- loader mappings: 2 float4 per thread for each of A and B ----
    int arow_[2], akoff_[2];
    long baseA_[2], baseS_[2];
    bool validA_[2];
    int bk_[2], bcol_[2];
#pragma unroll
    for (int i = 0; i < 2; i++) {
        int idx = i * 256 + tid;
        arow_[i]  = idx >> 2;
        akoff_[i] = (idx & 3) * 4;
        int r = bm + arow_[i];
        validA_[i] = (r < MVAL);
        if (MODE == 0) {
            baseA_[i] = (long)r * D;
            baseS_[i] = (long)r * DPOS;
        } else {
            int rr = validA_[i] ? r : 0;
            int b_l = rr / NVAL, n = rr - b_l * NVAL;
            baseA_[i] = ((long)b_l * NPAD + n) * D;
            baseS_[i] = 0;
        }
        bk_[i]   = idx >> 5;
        bcol_[i] = (idx & 31) * 4;
    }

    const float* Wp;
    int wbase;
    if (MODE == 1 && bn >= 256) { Wp = W1; wbase = bn - 256; }
    else                         { Wp = W0; wbase = bn; }

    float4 aReg[2], bReg[2];

    auto load_gmem = [&](int kt) {
#pragma unroll
        for (int i = 0; i < 2; i++) {
            int kk = kt + akoff_[i];
            if (MODE == 0) {
                if (!validA_[i]) aReg[i] = make_float4(0.f, 0.f, 0.f, 0.f);
                else if (kk < D) aReg[i] = *(const float4*)(P0 + baseA_[i] + kk);
                else             aReg[i] = *(const float4*)(P1 + baseS_[i] + (kk - D));
            } else if (MODE == 1) {
                aReg[i] = *(const float4*)(g_h + baseA_[i] + kk);
            } else {
                aReg[i] = *(const float4*)(g_hcomb + baseA_[i] + kk);
            }
            bReg[i] = *(const float4*)(Wp + (long)(kt + bk_[i]) * D + wbase + bcol_[i]);
        }
    };
    auto store_smem = [&](int buf) {
#pragma unroll
        for (int i = 0; i < 2; i++) {
            As[buf][akoff_[i] + 0][arow_[i]] = aReg[i].x;
            As[buf][akoff_[i] + 1][arow_[i]] = aReg[i].y;
            As[buf][akoff_[i] + 2][arow_[i]] = aReg[i].z;
            As[buf][akoff_[i] + 3][arow_[i]] = aReg[i].w;
            *(float4*)(&Bs[buf][bk_[i]][bcol_[i]]) = bReg[i];
        }
    };

    const int ty = tid >> 4;
    const int tx = tid & 15;

    u64 acc2[2][2][4][2];
#pragma unroll
    for (int gi = 0; gi < 2; gi++)
#pragma unroll
        for (int gj = 0; gj < 2; gj++)
#pragma unroll
            for (int i = 0; i < 4; i++) {
                acc2[gi][gj][i][0] = 0ULL;
                acc2[gi][gj][i][1] = 0ULL;
            }

    load_gmem(0);
    store_smem(0);
    __syncthreads();

    int buf = 0;
    for (int t = 0; t < NT; ++t) {
        if (t + 1 < NT) load_gmem((t + 1) * BK);
#pragma unroll
        for (int k = 0; k < BK; k++) {
            float4 a0 = *(const float4*)(&As[buf][k][ty * 4]);
            float4 a1 = *(const float4*)(&As[buf][k][64 + ty * 4]);
            float4 b0 = *(const float4*)(&Bs[buf][k][tx * 4]);
            float4 b1 = *(const float4*)(&Bs[buf][k][64 + tx * 4]);
            u64 bp[2][2] = {{pack2(b0.x, b0.y), pack2(b0.z, b0.w)},
                            {pack2(b1.x, b1.y), pack2(b1.z, b1.w)}};
            float av[2][4] = {{a0.x, a0.y, a0.z, a0.w}, {a1.x, a1.y, a1.z, a1.w}};
#pragma unroll
            for (int gi = 0; gi < 2; gi++)
#pragma unroll
                for (int i = 0; i < 4; i++) {
                    u64 ap = pack2(av[gi][i], av[gi][i]);
#pragma unroll
                    for (int gj = 0; gj < 2; gj++) {
                        acc2[gi][gj][i][0] = fma2(ap, bp[gj][0], acc2[gi][gj][i][0]);
                        acc2[gi][gj][i][1] = fma2(ap, bp[gj][1], acc2[gi][gj][i][1]);
                    }
                }
        }
        if (t + 1 < NT) {
            store_smem(buf ^ 1);
            __syncthreads();
            buf ^= 1;
        }
    }

    // ---- epilogue (valid rows only) ----
#pragma unroll
    for (int gi = 0; gi < 2; gi++)
#pragma unroll
    for (int i = 0; i < 4; i++) {
        int ro = bm + gi * 64 + ty * 4 + i;
        if (ro >= MVAL) continue;
#pragma unroll
        for (int gj = 0; gj < 2; gj++) {
            int cb = bn + gj * 64 + tx * 4;
            float c0, c1, c2, c3;
            unpack2(acc2[gi][gj][i][0], c0, c1);
            unpack2(acc2[gi][gj][i][1], c2, c3);

            if (MODE == 0) {
                int b_l = ro / NVAL, n = ro - b_l * NVAL;
                *(float4*)(g_h + ((long)b_l * NPAD + n) * D + cb) =
                    make_float4(c0 + bias[cb + 0], c1 + bias[cb + 1],
                                c2 + bias[cb + 2], c3 + bias[cb + 3]);
            } else if (MODE == 1) {
                int b_l = ro / NVAL, n = ro - b_l * NVAL;
                int cc = cb;
                float* dst;
                if (cc < D) { int head = cc >> 5; int e = cc & 31;
                    dst = g_qk + ((long)((b_l << 3) + head) * NPAD + n) * EDIM + e; }
                else { cc -= D; int head = cc >> 5; int e = cc & 31;
                    dst = g_v  + ((long)((b_l << 3) + head) * NPAD + n) * EDIM + e; }
                *(float4*)(dst) = make_float4(c0, c1, c2, c3);
            } else {
                *(float4*)(Cout + (long)ro * D + cb) =
                    make_float4(c0 + bias[cb + 0], c1 + bias[cb + 1],
                                c2 + bias[cb + 2], c3 + bias[cb + 3]);
            }
        }
    }
}

// ---------------- zero-fill pad-row qk/v ----------------------------------------
__global__ __launch_bounds__(256)
void zero_pad_qkv()
{
    int gid = blockIdx.x * 256 + threadIdx.x;
    const int total = BH * (NPAD - NVAL) * EDIM;
    if (gid >= total) return;
    int e  = gid & 31;
    int t  = gid >> 5;
    int pi = t % (NPAD - NVAL);
    int bh = t / (NPAD - NVAL);
    long off = ((long)bh * NPAD + NVAL + pi) * EDIM + e;
    g_qk[off] = 0.f;
    g_v[off]  = 0.f;
}

// ---------------- hashing: rot = qk @ rotations, argmax over [rot,-rot] -------
__global__ __launch_bounds__(256)
void hash_kernel(const float* __restrict__ rot)
{
    __shared__ u64 srot2[EDIM][NH][6];
    int tid = threadIdx.x;
    for (int i = tid; i < EDIM * NH * 6; i += blockDim.x) {
        int e  = i / (NH * 6);
        int h  = (i / 6) % NH;
        int rr = i % 6;
        int r0 = 2 * rr, r1 = 2 * rr + 1;
        float xv = (r0 < NB / 2) ? rot[(e * NH + h) * (NB / 2) + r0] : 0.f;
        float yv = (r1 < NB / 2) ? rot[(e * NH + h) * (NB / 2) + r1] : 0.f;
        srot2[e][h][rr] = pack2(xv, yv);
    }
    __syncthreads();

    int gid = blockIdx.x * blockDim.x + tid;
    if (gid >= BH * NPAD) return;
    int bh = gid / NPAD;
    int n  = gid - bh * NPAD;

    float q[EDIM];
    const float* qp = &g_qk[(long)(bh * NPAD + n) * EDIM];
#pragma unroll
    for (int e = 0; e < EDIM; e += 4) {
        float4 t = *(const float4*)(qp + e);
        q[e] = t.x; q[e + 1] = t.y; q[e + 2] = t.z; q[e + 3] = t.w;
    }

    for (int h = 0; h < NH; h++) {
        u64 s2[6];
#pragma unroll
        for (int rr = 0; rr < 6; rr++) s2[rr] = 0ULL;
#pragma unroll
        for (int e = 0; e < EDIM; e++) {
            u64 qq = pack2(q[e], q[e]);
#pragma unroll
            for (int rr = 0; rr < 6; rr++)
                s2[rr] = fma2(qq, srot2[e][h][rr], s2[rr]);
        }
        float rv[12];
#pragma unroll
        for (int rr = 0; rr < 6; rr++) unpack2(s2[rr], rv[2 * rr], rv[2 * rr + 1]);

        float best = rv[0];
        int bi = 0;
#pragma unroll
        for (int r = 1; r < NB / 2; r++)
            if (rv[r] > best) { best = rv[r]; bi = r; }
#pragma unroll
        for (int r = 0; r < NB / 2; r++)
            if (-rv[r] > best) { best = -rv[r]; bi = r + NB / 2; }
        g_bucket[bh * NS + h * NPAD + n] = bi + h * NB;
    }
}

// ---------------- stable counting sort per bh (88 buckets, 1408 items) --------
__global__ __launch_bounds__(128)
void sort_kernel()
{
    const int bh  = blockIdx.x;
    const int tid = threadIdx.x;

    __shared__ unsigned short hist[128][89];
    __shared__ int sbuck[NS];
    __shared__ int base[NC];
    __shared__ int tot[NC];

    for (int i = tid; i < NS; i += 128) sbuck[i] = g_bucket[bh * NS + i];
    for (int b = 0; b < NC; b++) hist[tid][b] = 0;
    __syncthreads();

#pragma unroll
    for (int k = 0; k < NS / 128; k++) {
        int i = tid * (NS / 128) + k;
        hist[tid][sbuck[i]]++;
    }
    __syncthreads();

    if (tid < NC) {
        int s = 0;
        for (int t = 0; t < 128; t++) s += hist[t][tid];
        tot[tid] = s;
    }
    __syncthreads();
    if (tid == 0) {
        int run = 0;
        for (int b = 0; b < NC; b++) { base[b] = run; run += tot[b]; }
    }
    __syncthreads();
    if (tid < NC) {
        int run = base[tid];
        for (int t = 0; t < 128; t++) {
            int c = hist[t][tid];
            hist[t][tid] = (unsigned short)run;
            run += c;
        }
    }
    __syncthreads();

#pragma unroll
    for (int k = 0; k < NS / 128; k++) {
        int i = tid * (NS / 128) + k;
        int b = sbuck[i];
        int pos = hist[tid][b]++;
        g_sticker[bh * NS + pos] = i;
    }
}

// ---------------- persistent per-bh attention -----------------------------------
// One block per bh: cache full qk/v slice (stride 33 vs bank conflicts), sticker,
// per-row norms (computed once, same fmaf order as before); loop all 88 chunks.
#define ATTN_SMEM ((2*352*33 + 352) * 4 + NS * 4 + 2*32*34*4)

__global__ __launch_bounds__(512)
void attn_kernel()
{
    extern __shared__ __align__(16) float sm[];
    float* cq     = sm;                      // 352*33
    float* cv     = cq + 352 * 33;           // 352*33
    float* rn_all = cv + 352 * 33;           // 352
    int*   st     = (int*)(rn_all + 352);    // 1408
    float (*kq)[34] = (float(*)[34])(st + NS);          // 32*34
    float (*vv)[34] = (float(*)[34])((float*)(st + NS) + 32 * 34);

    __shared__ int   nn[32];
    __shared__ int   hh[32];
    __shared__ float rnc[32];

    const int bh   = blockIdx.x;
    const int tid  = threadIdx.x;
    const int warp = tid >> 5;
    const int lane = tid & 31;

    // load sticker slice
    for (int i = tid; i < NS; i += 512) st[i] = g_sticker[bh * NS + i];
    // load qk/v slice into stride-33 cache
    for (int i = tid; i < 352 * 8; i += 512) {
        int row = i >> 3, q = (i & 7) * 4;
        long off = ((long)bh * NPAD + row) * EDIM + q;
        float4 a = *(const float4*)(g_qk + off);
        float4 b = *(const float4*)(g_v + off);
        float* dq = cq + row * 33 + q;
        dq[0] = a.x; dq[1] = a.y; dq[2] = a.z; dq[3] = a.w;
        float* dv = cv + row * 33 + q;
        dv[0] = b.x; dv[1] = b.y; dv[2] = b.z; dv[3] = b.w;
    }
    __syncthreads();

    // per-row norms, once (even/odd split replicates the f32x2 lane order)
    for (int row = tid; row < NPAD; row += 512) {
        float se = 0.f, so = 0.f;
        const float* rp = cq + row * 33;
#pragma unroll
        for (int e2 = 0; e2 < EDIM / 2; e2++) {
            se = fmaf(rp[2 * e2],     rp[2 * e2],     se);
            so = fmaf(rp[2 * e2 + 1], rp[2 * e2 + 1], so);
        }
        float s = sqrtf(se + so);
        rn_all[row] = 1.0f / fmaxf(s, 1e-12f);
    }
    __syncthreads();

    for (int c = 0; c < NC; c++) {
        if (tid < 32) {
            int cj   = (tid < BKTS) ? c : (c + NC - 1) % NC;
            int item = st[cj * BKTS + (tid & (BKTS - 1))];
            int n    = item % NPAD;
            nn[tid]  = n;
            hh[tid]  = item / NPAD;
            rnc[tid] = rn_all[n];
        }
        __syncthreads();

        // stage chunk rows into aligned buffers (lane = e -> conflict-light)
        {
            int j0 = warp, j1 = warp + 16;
            kq[j0][lane] = cq[nn[j0] * 33 + lane];
            vv[j0][lane] = cv[nn[j0] * 33 + lane];
            kq[j1][lane] = cq[nn[j1] * 33 + lane];
            vv[j1][lane] = cv[nn[j1] * 33 + lane];
        }
        __syncthreads();

        const int i = warp;
        const int j = lane;

        u64 d2 = 0ULL;
#pragma unroll
        for (int e2 = 0; e2 < EDIM / 2; e2++) {
            u64 qa = *(const u64*)(&kq[i][2 * e2]);
            u64 kb = *(const u64*)(&kq[j][2 * e2]);
            d2 = fma2(qa, kb, d2);
        }
        float dl, dh2; unpack2(d2, dl, dh2);
        float d = (dl + dh2) * rnc[j] * 0.17677669529663687f;
        if (nn[i] == nn[j]) d = -50000.0f;

        float m = d;
#pragma unroll
        for (int o = 16; o > 0; o >>= 1) m = fmaxf(m, __shfl_xor_sync(0xffffffffu, m, o));
        float ex = expf(d - m);
        float sum = ex;
#pragma unroll
        for (int o = 16; o > 0; o >>= 1) sum += __shfl_xor_sync(0xffffffffu, sum, o);
        float lse = m + logf(sum);
        float p = ex / sum;

        float accv = 0.f;
#pragma unroll
        for (int jj = 0; jj < 32; jj++) {
            float pj = __shfl_sync(0xffffffffu, p, jj);
            accv += pj * vv[jj][lane];
        }

        int n_i = nn[i], h_i = hh[i];
        g_o[((long)(bh * NH + h_i) * NPAD + n_i) * EDIM + lane] = accv;
        if (lane == 0) g_lse[(bh * NH + h_i) * NPAD + n_i] = lse;
        __syncthreads();   // chunk buffers reused next iteration
    }
}

// ---------------- combine hashes (valid rows only) ------------------------------
__global__ __launch_bounds__(256)
void combine_kernel()
{
    int gid  = blockIdx.x * blockDim.x + threadIdx.x;
    int wid  = gid >> 5;
    int lane = gid & 31;
    if (wid >= BH * NPAD) return;
    int bh = wid / NPAD;
    int n  = wid - bh * NPAD;
    if (n >= NVAL) return;   // pad rows never read downstream

    float l0 = g_lse[(bh * NH + 0) * NPAD + n];
    float l1 = g_lse[(bh * NH + 1) * NPAD + n];
    float l2 = g_lse[(bh * NH + 2) * NPAD + n];
    float l3 = g_lse[(bh * NH + 3) * NPAD + n];
    float m = fmaxf(fmaxf(l0, l1), fmaxf(l2, l3));
    float e0 = expf(l0 - m), e1 = expf(l1 - m), e2 = expf(l2 - m), e3 = expf(l3 - m);
    float inv = 1.0f / (e0 + e1 + e2 + e3);

    float acc =
        e0 * inv * g_o[((long)(bh * NH + 0) * NPAD + n) * EDIM + lane] +
        e1 * inv * g_o[((long)(bh * NH + 1) * NPAD + n) * EDIM + lane] +
        e2 * inv * g_o[((long)(bh * NH + 2) * NPAD + n) * EDIM + lane] +
        e3 * inv * g_o[((long)(bh * NH + 3) * NPAD + n) * EDIM + lane];

    int b_l = bh >> 3, head = bh & 7;
    g_hcomb[(long)(b_l * NPAD + n) * D + head * EDIM + lane] = acc;
}

// ---------------- launch --------------------------------------------------------
extern "C" void kernel_launch(void* const* d_in, const int* in_sizes, int n_in,
                              void* d_out, int out_size)
{
    const float* x      = (const float*)d_in[0];
    const float* ste    = (const float*)d_in[1];
    const float* w_proj = (const float*)d_in[2];
    const float* b_proj = (const float*)d_in[3];
    const float* w_qk   = (const float*)d_in[4];
    const float* w_v    = (const float*)d_in[5];
    const float* w_out  = (const float*)d_in[6];
    const float* b_out  = (const float*)d_in[7];
    const float* rots   = (const float*)d_in[8];
    float* out = (float*)d_out;

    cudaFuncSetAttribute(attn_kernel, cudaFuncAttributeMaxDynamicSharedMemorySize,
                         ATTN_SMEM);

    gemm_k<0><<<dim3(GRIDM, 2), 256>>>(x, ste, w_proj, nullptr, b_proj, nullptr);
    gemm_k<1><<<dim3(GRIDM, 4), 256>>>(nullptr, nullptr, w_qk, w_v, nullptr, nullptr);
    zero_pad_qkv<<<(BH * (NPAD - NVAL) * EDIM + 255) / 256, 256>>>();
    hash_kernel<<<(BH * NPAD + 255) / 256, 256>>>(rots);
    sort_kernel<<<BH, 128>>>();
    attn_kernel<<<BH, 512, ATTN_SMEM>>>();
    combine_kernel<<<(BH * NPAD * 32 + 255) / 256, 256>>>();
    gemm_k<2><<<dim3(GRIDM, 2), 256>>>(nullptr, nullptr, w_out, nullptr, b_out, out);
}